// round 1
// baseline (speedup 1.0000x reference)
#include <cuda_runtime.h>
#include <cuda_bf16.h>

// SpatialGraphConv: out = relu( bn1(gcn_w@x @ Ae) + bn2(res_w@x) )
// Folded: out[n,o,m] = relu( sum_c Wt[o,c]*Z[c,m] + bo[o] + g1b[o]*sumAe[m%25] )
//   Z[c<64]  = x[n,c,:]        (res branch, Wt = inv2*res_w)
//   Z[c>=64] = xA[n,c-64,:]    (gcn branch, Wt = inv1*gcn_w),  xA = x @ (A*edge) over V
// N=64 Cin=64 Cout=128 T=300 V=25, m = t*25+v in [0,7500)

#define NB   64
#define CIN  64
#define COUT 128
#define TT   300
#define VV   25
#define MTOT (TT*VV)          // 7500
#define ROWS (NB*CIN*TT)      // 1228800

__device__ float g_xA[NB*CIN*TT*VV];   // 122.88 MB scratch
__device__ float g_W[COUT*128];        // [o][c'] tf32-rounded, c'<64 res, c'>=64 gcn
__device__ float g_bo[COUT];
__device__ float g_g1b[COUT];
__device__ float g_Ae[VV*VV];
__device__ float g_sumAe[VV];

__device__ __forceinline__ unsigned tf32_bits(float f) {
    unsigned u;
    asm("cvt.rna.tf32.f32 %0, %1;" : "=r"(u) : "f"(f));
    return u;
}

__device__ __forceinline__ void fma2(unsigned long long& acc, unsigned long long x2, unsigned long long a2) {
    asm("fma.rn.f32x2 %0, %1, %2, %0;" : "+l"(acc) : "l"(x2), "l"(a2));
}

__device__ __forceinline__ void mma_tf32(float* c, const unsigned* a, const unsigned* b) {
    asm volatile(
        "mma.sync.aligned.m16n8k8.row.col.f32.tf32.tf32.f32 "
        "{%0,%1,%2,%3}, {%4,%5,%6,%7}, {%8,%9}, {%0,%1,%2,%3};"
        : "+f"(c[0]), "+f"(c[1]), "+f"(c[2]), "+f"(c[3])
        : "r"(a[0]), "r"(a[1]), "r"(a[2]), "r"(a[3]), "r"(b[0]), "r"(b[1]));
}

// ---------------- prep: fold BN into weights, build Ae / bias tables ----------------
__global__ void prep_kernel(const float* __restrict__ A, const float* __restrict__ edge,
                            const float* __restrict__ gcn_w, const float* __restrict__ gcn_b,
                            const float* __restrict__ bn_g, const float* __restrict__ bn_b,
                            const float* __restrict__ bn_m, const float* __restrict__ bn_v,
                            const float* __restrict__ res_w, const float* __restrict__ res_b,
                            const float* __restrict__ rbn_g, const float* __restrict__ rbn_b,
                            const float* __restrict__ rbn_m, const float* __restrict__ rbn_v) {
    int tid = threadIdx.x;
    for (int i = tid; i < VV*VV; i += 256) g_Ae[i] = A[i] * edge[i];
    __syncthreads();
    if (tid < VV) {
        float s = 0.f;
        for (int v = 0; v < VV; v++) s += g_Ae[v*VV + tid];
        g_sumAe[tid] = s;
    }
    if (tid < COUT) {
        int o = tid;
        float inv1 = bn_g[o]  * rsqrtf(bn_v[o]  + 1e-5f);
        float sh1  = bn_b[o]  - bn_m[o]  * inv1;
        float inv2 = rbn_g[o] * rsqrtf(rbn_v[o] + 1e-5f);
        float sh2  = rbn_b[o] - rbn_m[o] * inv2;
        g_bo[o]  = sh1 + sh2 + inv2 * res_b[o];
        g_g1b[o] = inv1 * gcn_b[o];
        for (int k = 0; k < CIN; k++)
            g_W[o*128 + k] = __uint_as_float(tf32_bits(inv2 * res_w[o*CIN + k]));
        for (int k = 0; k < CIN; k++)
            g_W[o*128 + 64 + k] = __uint_as_float(tf32_bits(inv1 * gcn_w[o*CIN + k]));
    }
}

// ---------------- xA = x @ Ae over V (per (n,c,t) row) ----------------
// block: 256 threads, 64 rows (1600 contiguous floats in). Each thread: one w column, 8 rows,
// packed f32x2 FMAs (fp32 FFMA rt=2 would be compute-bound otherwise).
__global__ __launch_bounds__(256) void xa_kernel(const float* __restrict__ x) {
    __shared__ __align__(16) float xsT[VV*64];   // [v][r]
    long long base = (long long)blockIdx.x * 64 * VV;
    for (int i = threadIdx.x; i < 64*VV; i += 256) {
        float val = x[base + i];
        int v = i % VV, r = i / VV;
        xsT[v*64 + r] = val;
    }
    __syncthreads();
    int w = threadIdx.x & 31;
    int rbase = (threadIdx.x >> 5) * 8;
    if (w < VV) {
        float ae[VV];
        #pragma unroll
        for (int v = 0; v < VV; v++) ae[v] = g_Ae[v*VV + w];
        unsigned long long acc[4] = {0ull, 0ull, 0ull, 0ull};
        #pragma unroll
        for (int v = 0; v < VV; v++) {
            unsigned ab = __float_as_uint(ae[v]);
            unsigned long long a2 = ((unsigned long long)ab << 32) | (unsigned long long)ab;
            const unsigned long long* p =
                reinterpret_cast<const unsigned long long*>(&xsT[v*64 + rbase]);
            fma2(acc[0], p[0], a2);
            fma2(acc[1], p[1], a2);
            fma2(acc[2], p[2], a2);
            fma2(acc[3], p[3], a2);
        }
        long long rowg = (long long)blockIdx.x * 64 + rbase;
        #pragma unroll
        for (int q = 0; q < 4; q++) {
            g_xA[(rowg + 2*q)     * VV + w] = __uint_as_float((unsigned)(acc[q] & 0xffffffffull));
            g_xA[(rowg + 2*q + 1) * VV + w] = __uint_as_float((unsigned)(acc[q] >> 32));
        }
    }
}

// ---------------- fused GEMM: out[128 o x 128 m] tile, K=128, tf32 mma ----------------
// 256 thr = 8 warps (4 o-warps x 2 m-warps); warp tile 32o x 64m; K-chunks of 32.
__global__ __launch_bounds__(256, 2) void gemm_kernel(const float* __restrict__ x,
                                                      float* __restrict__ out) {
    __shared__ __align__(16) float sW[128*36];   // [o][k] pad 4 -> conflict-free A frags
    __shared__ __align__(16) float sZ[32*132];   // [k][m] pad 4

    int n  = blockIdx.y;
    int m0 = blockIdx.x * 128;
    int mrem = MTOT - m0;                        // valid cols in this tile (<=128)
    int tid = threadIdx.x;
    int lane = tid & 31, wid = tid >> 5;
    int gid = lane >> 2, tig = lane & 3;
    int ob = (wid & 3) * 32;
    int mb = (wid >> 2) * 64;

    float acc[2][8][4];
    #pragma unroll
    for (int i = 0; i < 2; i++)
        #pragma unroll
        for (int j = 0; j < 8; j++)
            #pragma unroll
            for (int k = 0; k < 4; k++) acc[i][j][k] = 0.f;

    for (int kc = 0; kc < 4; kc++) {
        // W chunk: 128 o x 32 k
        #pragma unroll
        for (int i = 0; i < 4; i++) {
            int f4 = tid + 256*i;                 // < 1024
            int o = f4 >> 3, k = (f4 & 7) * 4;
            float4 wv = *reinterpret_cast<const float4*>(&g_W[o*128 + kc*32 + k]);
            *reinterpret_cast<float4*>(&sW[o*36 + k]) = wv;
        }
        // Z chunk: 32 c x 128 m (c<64 from x, else from g_xA), tf32-round on store
        #pragma unroll
        for (int i = 0; i < 4; i++) {
            int f4 = tid + 256*i;                 // < 1024
            int kk = f4 >> 5, j = (f4 & 31) * 4;
            int c = kc*32 + kk;
            const float* src = (c < CIN)
                ? (x    + (long long)(n*CIN + c)        * MTOT + m0)
                : (g_xA + (long long)(n*CIN + (c-CIN))  * MTOT + m0);
            float4 zv;
            if (j + 4 <= mrem) {
                zv = *reinterpret_cast<const float4*>(src + j);
            } else {
                zv.x = (j+0 < mrem) ? src[j+0] : 0.f;
                zv.y = (j+1 < mrem) ? src[j+1] : 0.f;
                zv.z = (j+2 < mrem) ? src[j+2] : 0.f;
                zv.w = (j+3 < mrem) ? src[j+3] : 0.f;
            }
            unsigned* d = reinterpret_cast<unsigned*>(&sZ[kk*132 + j]);
            d[0] = tf32_bits(zv.x); d[1] = tf32_bits(zv.y);
            d[2] = tf32_bits(zv.z); d[3] = tf32_bits(zv.w);
        }
        __syncthreads();

        const unsigned* sWu = reinterpret_cast<const unsigned*>(sW);
        const unsigned* sZu = reinterpret_cast<const unsigned*>(sZ);
        #pragma unroll
        for (int k8 = 0; k8 < 4; k8++) {
            unsigned a[2][4], b[8][2];
            #pragma unroll
            for (int os = 0; os < 2; os++) {
                int r0 = ob + os*16 + gid;
                a[os][0] = sWu[ r0     *36 + k8*8 + tig    ];
                a[os][1] = sWu[(r0 + 8)*36 + k8*8 + tig    ];
                a[os][2] = sWu[ r0     *36 + k8*8 + tig + 4];
                a[os][3] = sWu[(r0 + 8)*36 + k8*8 + tig + 4];
            }
            #pragma unroll
            for (int ms = 0; ms < 8; ms++) {
                int col = mb + ms*8 + gid;
                b[ms][0] = sZu[(k8*8 + tig    )*132 + col];
                b[ms][1] = sZu[(k8*8 + tig + 4)*132 + col];
            }
            #pragma unroll
            for (int os = 0; os < 2; os++)
                #pragma unroll
                for (int ms = 0; ms < 8; ms++)
                    mma_tf32(acc[os][ms], a[os], b[ms]);
        }
        __syncthreads();
    }

    // epilogue: bias + relu + store
    #pragma unroll
    for (int os = 0; os < 2; os++) {
        int r0 = ob + os*16 + gid;
        float bo0 = g_bo[r0],     gb0 = g_g1b[r0];
        float bo1 = g_bo[r0 + 8], gb1 = g_g1b[r0 + 8];
        long long base0 = (long long)(n*COUT + r0)     * MTOT + m0;
        long long base1 = (long long)(n*COUT + r0 + 8) * MTOT + m0;
        #pragma unroll
        for (int ms = 0; ms < 8; ms++) {
            int col = mb + ms*8 + tig*2;
            int mg = m0 + col;
            int w0 = mg % 25;
            int w1 = (w0 + 1 == 25) ? 0 : (w0 + 1);
            float s0 = g_sumAe[w0], s1 = g_sumAe[w1];
            float v00 = fmaxf(acc[os][ms][0] + bo0 + gb0*s0, 0.f);
            float v01 = fmaxf(acc[os][ms][1] + bo0 + gb0*s1, 0.f);
            float v10 = fmaxf(acc[os][ms][2] + bo1 + gb1*s0, 0.f);
            float v11 = fmaxf(acc[os][ms][3] + bo1 + gb1*s1, 0.f);
            if (col + 2 <= mrem) {
                *reinterpret_cast<float2*>(&out[base0 + col]) = make_float2(v00, v01);
                *reinterpret_cast<float2*>(&out[base1 + col]) = make_float2(v10, v11);
            } else {
                if (col < mrem)     { out[base0 + col]     = v00; out[base1 + col]     = v10; }
                if (col + 1 < mrem) { out[base0 + col + 1] = v01; out[base1 + col + 1] = v11; }
            }
        }
    }
}

extern "C" void kernel_launch(void* const* d_in, const int* in_sizes, int n_in,
                              void* d_out, int out_size) {
    const float* x     = (const float*)d_in[0];
    const float* A     = (const float*)d_in[1];
    const float* edge  = (const float*)d_in[2];
    const float* gcn_w = (const float*)d_in[3];
    const float* gcn_b = (const float*)d_in[4];
    const float* bn_g  = (const float*)d_in[5];
    const float* bn_b  = (const float*)d_in[6];
    const float* bn_m  = (const float*)d_in[7];
    const float* bn_v  = (const float*)d_in[8];
    const float* res_w = (const float*)d_in[9];
    const float* res_b = (const float*)d_in[10];
    const float* rbn_g = (const float*)d_in[11];
    const float* rbn_b = (const float*)d_in[12];
    const float* rbn_m = (const float*)d_in[13];
    const float* rbn_v = (const float*)d_in[14];
    float* out = (float*)d_out;

    prep_kernel<<<1, 256>>>(A, edge, gcn_w, gcn_b, bn_g, bn_b, bn_m, bn_v,
                            res_w, res_b, rbn_g, rbn_b, rbn_m, rbn_v);
    xa_kernel<<<ROWS/64, 256>>>(x);
    gemm_kernel<<<dim3((MTOT + 127)/128, NB), 256>>>(x, out);
}

// round 5
// speedup vs baseline: 1.5379x; 1.5379x over previous
#include <cuda_runtime.h>

// SpatialGraphConv fused: out[n,o,m] = relu( sum_c W[o,c]*Z[c,m] + bo[o] + g1b[o]*sumAe[m%25] )
//   Z rows 0..63   = x[n,c,m]                 (res branch, W = inv2*res_w)
//   Z rows 64..127 = xA[n,c,m] = x @ Ae (V)   (gcn branch, W = inv1*gcn_w)
// N=64 Cin=64 Cout=128 T=300 V=25, m in [0,7500). Tiles: 125 m-cols (5 t-groups) x 128 o.
// Persistent kernel, 148 blocks, double-buffered cp.async, xA via stage-1 tf32 MMA in smem.
// NOTE: odd tiles have odd m0 -> scalar stores (STG.64 at odd float offset traps).

#define NTILES (64*60)     // 64 n * 60 m-tiles
#define MTOT   7500

__device__ float g_W[128*128];     // tf32 bits, [o][k]: k<64 res, k>=64 gcn
__device__ float g_bo[128];
__device__ float g_g1b[128];
__device__ float g_Ae32[32*32];    // tf32 bits, zero-padded Ae[v][w]
__device__ float g_sumAe[32];

static __device__ __forceinline__ unsigned tf32_bits(float f) {
    unsigned u; asm("cvt.rna.tf32.f32 %0, %1;" : "=r"(u) : "f"(f)); return u;
}

static __device__ __forceinline__ void mma_tf32(float* c, const unsigned* a, const unsigned* b) {
    asm volatile(
        "mma.sync.aligned.m16n8k8.row.col.f32.tf32.tf32.f32 "
        "{%0,%1,%2,%3}, {%4,%5,%6,%7}, {%8,%9}, {%0,%1,%2,%3};"
        : "+f"(c[0]), "+f"(c[1]), "+f"(c[2]), "+f"(c[3])
        : "r"(a[0]), "r"(a[1]), "r"(a[2]), "r"(a[3]), "r"(b[0]), "r"(b[1]));
}

// ---------------- prep: parallel fold of BN into weights + tables ----------------
__global__ void prep_kernel(const float* __restrict__ A, const float* __restrict__ edge,
                            const float* __restrict__ gcn_w, const float* __restrict__ gcn_b,
                            const float* __restrict__ bn_g, const float* __restrict__ bn_b,
                            const float* __restrict__ bn_m, const float* __restrict__ bn_v,
                            const float* __restrict__ res_w, const float* __restrict__ res_b,
                            const float* __restrict__ rbn_g, const float* __restrict__ rbn_b,
                            const float* __restrict__ rbn_m, const float* __restrict__ rbn_v) {
    int b = blockIdx.x, tid = threadIdx.x;
    if (b < 128) {
        int o = b;
        float inv1 = bn_g[o]  * rsqrtf(bn_v[o]  + 1e-5f);
        float inv2 = rbn_g[o] * rsqrtf(rbn_v[o] + 1e-5f);
        int k = tid;   // 64 threads
        g_W[o*128 + k]      = __uint_as_float(tf32_bits(inv2 * res_w[o*64 + k]));
        g_W[o*128 + 64 + k] = __uint_as_float(tf32_bits(inv1 * gcn_w[o*64 + k]));
        if (tid == 0) {
            float sh1 = bn_b[o]  - bn_m[o]  * inv1;
            float sh2 = rbn_b[o] - rbn_m[o] * inv2;
            g_bo[o]  = sh1 + sh2 + inv2 * res_b[o];
            g_g1b[o] = inv1 * gcn_b[o];
        }
    } else if (b == 128) {
        for (int i = tid; i < 1024; i += 64) {
            int v = i >> 5, w = i & 31;
            g_Ae32[i] = (v < 25 && w < 25)
                ? __uint_as_float(tf32_bits(A[v*25 + w] * edge[v*25 + w])) : 0.f;
        }
    } else {
        if (tid < 32) {
            float s = 0.f;
            if (tid < 25)
                for (int v = 0; v < 25; v++) s += A[v*25 + tid] * edge[v*25 + tid];
            g_sumAe[tid] = s;
        }
    }
}

// ---------------- fused persistent kernel ----------------
// smem layout (floats):
#define SW_OFF   0         // W 128x132
#define XB0_OFF  16896     // x buf0 64x132 (fp32 -> tf32 in place)
#define XB1_OFF  25344     // x buf1
#define XA_OFF   33792     // xA 64x132 (tf32)
#define AE_OFF   42240     // Ae 32x36 (tf32, zero padded)
#define BO_OFF   43392
#define G1_OFF   43520
#define SUM_OFF  43648
#define SMEM_FLOATS 43680

extern __shared__ float smem[];

static __device__ __forceinline__ void issue_tile(const float* __restrict__ x,
                                                  float* __restrict__ dst, int t) {
    int n = t / 60, mt = t - n * 60;
    int m0a = (mt * 125) & ~3;                      // 16B-aligned base, m0a+128 <= 7500 always
    const float* src = x + (size_t)n * 64 * MTOT + m0a;
    #pragma unroll
    for (int j = 0; j < 8; j++) {
        int i = threadIdx.x + 256 * j;              // < 2048
        int c = i >> 5, q = (i & 31) * 4;
        const float* g = src + (size_t)c * MTOT + q;
        unsigned saddr = (unsigned)__cvta_generic_to_shared(dst + c * 132 + q);
        asm volatile("cp.async.cg.shared.global [%0], [%1], 16;\n"
                     :: "r"(saddr), "l"(g));
    }
}

__global__ __launch_bounds__(256) void fused_kernel(const float* __restrict__ x,
                                                    float* __restrict__ out) {
    float* sW  = smem + SW_OFF;
    float* xb0 = smem + XB0_OFF;
    float* xb1 = smem + XB1_OFF;
    float* sxA = smem + XA_OFF;
    float* sAe = smem + AE_OFF;

    int tid = threadIdx.x, lane = tid & 31, wid = tid >> 5;
    int gid = lane >> 2, tig = lane & 3;
    int ob = (wid & 3) * 32, mb = (wid >> 2) * 64;

    // ---- one-time init: W, Ae, bias tables, zero pads ----
    for (int i = tid; i < 4096; i += 256) {         // 4096 float4s of W
        float4 w4 = *reinterpret_cast<const float4*>(&g_W[i * 4]);
        *reinterpret_cast<float4*>(&sW[(i >> 5) * 132 + (i & 31) * 4]) = w4;
    }
    for (int i = tid; i < 1024; i += 256)
        sAe[(i >> 5) * 36 + (i & 31)] = g_Ae32[i];
    if (tid < 128) { smem[BO_OFF + tid] = g_bo[tid]; smem[G1_OFF + tid] = g_g1b[tid]; }
    if (tid < 32)  { smem[SUM_OFF + tid] = g_sumAe[tid]; }
    for (int i = tid; i < 768; i += 256) {          // zero pad cols 128..131 of xb0/xb1/xA
        int bi = i >> 8, j = i & 255;
        float* p = (bi == 0) ? xb0 : (bi == 1) ? xb1 : sxA;
        p[(j >> 2) * 132 + 128 + (j & 3)] = 0.f;
    }

    // ---- prologue ----
    int t = blockIdx.x;
    if (t < NTILES) issue_tile(x, xb0, t);
    asm volatile("cp.async.commit_group;");

    int buf = 0;
    for (; t < NTILES; t += gridDim.x) {
        int tn = t + gridDim.x;
        if (tn < NTILES) issue_tile(x, (buf ? xb0 : xb1), tn);
        asm volatile("cp.async.commit_group;");
        asm volatile("cp.async.wait_group 1;");
        __syncthreads();                            // x[buf] ready (+ init on first iter)

        int n = t / 60, mt = t - n * 60;
        int m0 = mt * 125;
        int dlt = m0 & 3;                           // smem col = logical col + dlt

        float*    xbc = buf ? xb1 : xb0;
        unsigned* xbu = reinterpret_cast<unsigned*>(xbc);

        // ---- convert x tile fp32 -> tf32 in place ----
        #pragma unroll
        for (int j = 0; j < 8; j++) {
            int i = tid + 256 * j;
            int off = (i >> 5) * 132 + (i & 31) * 4;
            float4 v = *reinterpret_cast<float4*>(&xbc[off]);
            uint4 r;
            r.x = tf32_bits(v.x); r.y = tf32_bits(v.y);
            r.z = tf32_bits(v.z); r.w = tf32_bits(v.w);
            *reinterpret_cast<uint4*>(&xbu[off]) = r;
        }
        __syncthreads();

        // ---- stage 1: xA = x @ Ae via tf32 MMA (20 units = 5 tg x 4 row-tiles) ----
        // x frag cols beyond the 25-wide t-group hit Ae's zero-padded v-rows (finite*0).
        unsigned* sAeU = reinterpret_cast<unsigned*>(sAe);
        unsigned* sxAu = reinterpret_cast<unsigned*>(sxA);
        for (int u = wid; u < 20; u += 8) {
            int tg = u >> 2, m16 = u & 3;
            int r0 = m16 * 16 + gid;
            float a1[4][4];
            #pragma unroll
            for (int nt = 0; nt < 4; nt++)
                #pragma unroll
                for (int q = 0; q < 4; q++) a1[nt][q] = 0.f;
            #pragma unroll
            for (int k8 = 0; k8 < 4; k8++) {
                int cb = tg * 25 + dlt + k8 * 8;
                unsigned a[4];
                a[0] = xbu[ r0      * 132 + cb + tig];
                a[1] = xbu[(r0 + 8) * 132 + cb + tig];
                a[2] = xbu[ r0      * 132 + cb + tig + 4];
                a[3] = xbu[(r0 + 8) * 132 + cb + tig + 4];
                #pragma unroll
                for (int nt = 0; nt < 4; nt++) {
                    unsigned b[2];
                    b[0] = sAeU[(k8*8 + tig    ) * 36 + nt*8 + gid];
                    b[1] = sAeU[(k8*8 + tig + 4) * 36 + nt*8 + gid];
                    mma_tf32(a1[nt], a, b);
                }
            }
            int colb = tg * 25 + dlt;
            #pragma unroll
            for (int nt = 0; nt < 4; nt++) {
                int w0 = nt * 8 + tig * 2;
                if (w0 < 25) {
                    sxAu[ r0      * 132 + colb + w0] = tf32_bits(a1[nt][0]);
                    sxAu[(r0 + 8) * 132 + colb + w0] = tf32_bits(a1[nt][2]);
                }
                if (w0 + 1 < 25) {
                    sxAu[ r0      * 132 + colb + w0 + 1] = tf32_bits(a1[nt][1]);
                    sxAu[(r0 + 8) * 132 + colb + w0 + 1] = tf32_bits(a1[nt][3]);
                }
            }
        }
        __syncthreads();

        // ---- main MMA: 128o x 128cols, K=128 (rows 0..63 x, 64..127 xA) ----
        float acc[2][8][4];
        #pragma unroll
        for (int i = 0; i < 2; i++)
            #pragma unroll
            for (int j = 0; j < 8; j++)
                #pragma unroll
                for (int q = 0; q < 4; q++) acc[i][j][q] = 0.f;

        unsigned* sWu = reinterpret_cast<unsigned*>(sW);
        #pragma unroll
        for (int k8 = 0; k8 < 16; k8++) {
            unsigned* Zb = (k8 < 8) ? xbu : sxAu;
            int kk = (k8 & 7) * 8;
            unsigned a[2][4];
            #pragma unroll
            for (int os = 0; os < 2; os++) {
                int r0 = ob + os * 16 + gid;
                a[os][0] = sWu[ r0      * 132 + k8*8 + tig    ];
                a[os][1] = sWu[(r0 + 8) * 132 + k8*8 + tig    ];
                a[os][2] = sWu[ r0      * 132 + k8*8 + tig + 4];
                a[os][3] = sWu[(r0 + 8) * 132 + k8*8 + tig + 4];
            }
            #pragma unroll
            for (int ms = 0; ms < 8; ms++) {
                int col = mb + ms * 8 + gid + dlt;
                unsigned b[2];
                b[0] = Zb[(kk + tig    ) * 132 + col];
                b[1] = Zb[(kk + tig + 4) * 132 + col];
                mma_tf32(acc[0][ms], a[0], b);
                mma_tf32(acc[1][ms], a[1], b);
            }
        }

        // ---- epilogue: bias + relu + store; float2 only when m0 even ----
        bool vec_ok = ((m0 & 1) == 0);
        #pragma unroll
        for (int os = 0; os < 2; os++) {
            int r0 = ob + os * 16 + gid;
            float bo0 = smem[BO_OFF + r0],     g0 = smem[G1_OFF + r0];
            float bo1 = smem[BO_OFF + r0 + 8], g1 = smem[G1_OFF + r0 + 8];
            size_t base0 = ((size_t)n * 128 + r0) * MTOT + m0;
            size_t base1 = base0 + (size_t)8 * MTOT;
            #pragma unroll
            for (int ms = 0; ms < 8; ms++) {
                int sc = mb + ms * 8 + tig * 2;
                if (sc >= 125) continue;
                int w0 = sc % 25;
                int w1 = (w0 == 24) ? 0 : w0 + 1;
                float s0 = smem[SUM_OFF + w0], s1 = smem[SUM_OFF + w1];
                float v00 = fmaxf(acc[os][ms][0] + bo0 + g0 * s0, 0.f);
                float v01 = fmaxf(acc[os][ms][1] + bo0 + g0 * s1, 0.f);
                float v10 = fmaxf(acc[os][ms][2] + bo1 + g1 * s0, 0.f);
                float v11 = fmaxf(acc[os][ms][3] + bo1 + g1 * s1, 0.f);
                if (vec_ok && sc + 2 <= 125) {
                    *reinterpret_cast<float2*>(&out[base0 + sc]) = make_float2(v00, v01);
                    *reinterpret_cast<float2*>(&out[base1 + sc]) = make_float2(v10, v11);
                } else {
                    out[base0 + sc] = v00;
                    out[base1 + sc] = v10;
                    if (sc + 1 < 125) {
                        out[base0 + sc + 1] = v01;
                        out[base1 + sc + 1] = v11;
                    }
                }
            }
        }
        __syncthreads();     // all reads of xb[buf]/sxA done before next overwrite
        buf ^= 1;
    }
}

extern "C" void kernel_launch(void* const* d_in, const int* in_sizes, int n_in,
                              void* d_out, int out_size) {
    const float* x     = (const float*)d_in[0];
    const float* A     = (const float*)d_in[1];
    const float* edge  = (const float*)d_in[2];
    const float* gcn_w = (const float*)d_in[3];
    const float* gcn_b = (const float*)d_in[4];
    const float* bn_g  = (const float*)d_in[5];
    const float* bn_b  = (const float*)d_in[6];
    const float* bn_m  = (const float*)d_in[7];
    const float* bn_v  = (const float*)d_in[8];
    const float* res_w = (const float*)d_in[9];
    const float* res_b = (const float*)d_in[10];
    const float* rbn_g = (const float*)d_in[11];
    const float* rbn_b = (const float*)d_in[12];
    const float* rbn_m = (const float*)d_in[13];
    const float* rbn_v = (const float*)d_in[14];
    float* out = (float*)d_out;

    cudaFuncSetAttribute(fused_kernel, cudaFuncAttributeMaxDynamicSharedMemorySize,
                         SMEM_FLOATS * 4);

    prep_kernel<<<130, 64>>>(A, edge, gcn_w, gcn_b, bn_g, bn_b, bn_m, bn_v,
                             res_w, res_b, rbn_g, rbn_b, rbn_m, rbn_v);
    fused_kernel<<<148, 256, SMEM_FLOATS * 4>>>(x, out);
}

// round 6
// speedup vs baseline: 1.6422x; 1.0678x over previous
#include <cuda_runtime.h>

// SpatialGraphConv fused: out[n,o,m] = relu( sum_c W[o,c]*Z[c,m] + bo[o] + g1b[o]*sumAe[m%25] )
//   Z rows 0..63   = x[n,c,m]                 (res branch, W = inv2*res_w)
//   Z rows 64..127 = xA[n,c,m] = x @ Ae (V)   (gcn branch, W = inv1*gcn_w)
// N=64 Cin=64 Cout=128 T=300 V=25, m in [0,7500). Tiles: 125 m-cols (5 t-groups) x 128 o.
// Persistent, 148 blocks x 512 thr. Z buffers stride 136 (bank-conflict-free b frags),
// W stored in mma-fragment order (a frags = 1 LDS.128), double-buffered cp.async.

#define NTILES (64*60)
#define MTOT   7500
#define ZS     136          // Z-buffer row stride (mod 32 == 8 -> conflict-free)
#define AS     40           // Ae row stride

__device__ float g_Wf[128*128];    // W in mma A-frag order: [((k8*8+o16)*32+lane)*4+reg]
__device__ float g_bo[128];
__device__ float g_g1b[128];
__device__ float g_Ae32[32*32];    // tf32 bits, zero-padded Ae[v][w]
__device__ float g_sumAe[32];

static __device__ __forceinline__ unsigned tf32_bits(float f) {
    unsigned u; asm("cvt.rna.tf32.f32 %0, %1;" : "=r"(u) : "f"(f)); return u;
}

static __device__ __forceinline__ void mma_tf32(float* c, const unsigned* a, const unsigned* b) {
    asm volatile(
        "mma.sync.aligned.m16n8k8.row.col.f32.tf32.tf32.f32 "
        "{%0,%1,%2,%3}, {%4,%5,%6,%7}, {%8,%9}, {%0,%1,%2,%3};"
        : "+f"(c[0]), "+f"(c[1]), "+f"(c[2]), "+f"(c[3])
        : "r"(a[0]), "r"(a[1]), "r"(a[2]), "r"(a[3]), "r"(b[0]), "r"(b[1]));
}

// ---------------- prep ----------------
__global__ void prep_kernel(const float* __restrict__ A, const float* __restrict__ edge,
                            const float* __restrict__ gcn_w, const float* __restrict__ gcn_b,
                            const float* __restrict__ bn_g, const float* __restrict__ bn_b,
                            const float* __restrict__ bn_m, const float* __restrict__ bn_v,
                            const float* __restrict__ res_w, const float* __restrict__ res_b,
                            const float* __restrict__ rbn_g, const float* __restrict__ rbn_b,
                            const float* __restrict__ rbn_m, const float* __restrict__ rbn_v) {
    int b = blockIdx.x, tid = threadIdx.x;
    if (b < 128) {
        int o = b;
        float inv1 = bn_g[o]  * rsqrtf(bn_v[o]  + 1e-5f);
        float inv2 = rbn_g[o] * rsqrtf(rbn_v[o] + 1e-5f);
        int o16 = o >> 4, orow = o & 15;
        int gid = orow & 7, half = orow >> 3;
        float wr = inv2 * res_w[o*64 + tid];    // k' = tid
        float wg = inv1 * gcn_w[o*64 + tid];    // k' = tid + 64
        #pragma unroll
        for (int s = 0; s < 2; s++) {
            int kp = tid + s*64;
            float w = s ? wg : wr;
            int k8 = kp >> 3, kc = kp & 7;
            int tig = kc & 3, ch = kc >> 2;
            g_Wf[(((k8*8 + o16)*32 + gid*4 + tig) << 2) + (half + 2*ch)]
                = __uint_as_float(tf32_bits(w));
        }
        if (tid == 0) {
            float sh1 = bn_b[o]  - bn_m[o]  * inv1;
            float sh2 = rbn_b[o] - rbn_m[o] * inv2;
            g_bo[o]  = sh1 + sh2 + inv2 * res_b[o];
            g_g1b[o] = inv1 * gcn_b[o];
        }
    } else if (b == 128) {
        for (int i = tid; i < 1024; i += 64) {
            int v = i >> 5, w = i & 31;
            g_Ae32[i] = (v < 25 && w < 25)
                ? __uint_as_float(tf32_bits(A[v*25 + w] * edge[v*25 + w])) : 0.f;
        }
    } else {
        if (tid < 32) {
            float s = 0.f;
            if (tid < 25)
                for (int v = 0; v < 25; v++) s += A[v*25 + tid] * edge[v*25 + tid];
            g_sumAe[tid] = s;
        }
    }
}

// ---------------- fused persistent kernel ----------------
// smem (floats):
#define SW_OFF   0                      // W frags 16384
#define XB0_OFF  16384                  // 64*136
#define XB1_OFF  (XB0_OFF + 64*ZS)      // 25088
#define XA_OFF   (XB1_OFF + 64*ZS)      // 33792
#define AE_OFF   (XA_OFF  + 64*ZS)      // 42496, 32*40
#define BO_OFF   (AE_OFF + 32*AS)       // 43776
#define G1_OFF   (BO_OFF + 128)
#define SUM_OFF  (G1_OFF + 128)
#define SMEM_FLOATS (SUM_OFF + 32)

extern __shared__ float smem[];

static __device__ __forceinline__ void issue_tile(const float* __restrict__ x,
                                                  float* __restrict__ dst, int t) {
    int n = t / 60, mt = t - n * 60;
    int m0a = (mt * 125) & ~3;                      // 16B-aligned base, m0a+128 <= 7500
    const float* src = x + (size_t)n * 64 * MTOT + m0a;
    #pragma unroll
    for (int j = 0; j < 4; j++) {
        int i = threadIdx.x + 512 * j;              // < 2048
        int c = i >> 5, q = (i & 31) * 4;
        const float* g = src + (size_t)c * MTOT + q;
        unsigned saddr = (unsigned)__cvta_generic_to_shared(dst + c * ZS + q);
        asm volatile("cp.async.cg.shared.global [%0], [%1], 16;\n" :: "r"(saddr), "l"(g));
    }
}

__global__ __launch_bounds__(512) void fused_kernel(const float* __restrict__ x,
                                                    float* __restrict__ out) {
    float* sWf = smem + SW_OFF;
    float* xb0 = smem + XB0_OFF;
    float* xb1 = smem + XB1_OFF;
    float* sxA = smem + XA_OFF;
    float* sAe = smem + AE_OFF;

    int tid = threadIdx.x, lane = tid & 31, wid = tid >> 5;   // 16 warps
    int gid = lane >> 2, tig = lane & 3;
    int ob = (wid & 3) * 32, mb = (wid >> 2) * 32;

    // ---- one-time init ----
    for (int i = tid; i < 4096; i += 512)           // W frags: straight copy
        *reinterpret_cast<float4*>(&sWf[i * 4]) =
            *reinterpret_cast<const float4*>(&g_Wf[i * 4]);
    for (int i = tid; i < 1024; i += 512)
        sAe[(i >> 5) * AS + (i & 31)] = g_Ae32[i];
    if (tid < 128) { smem[BO_OFF + tid] = g_bo[tid]; smem[G1_OFF + tid] = g_g1b[tid]; }
    if (tid < 32)  { smem[SUM_OFF + tid] = g_sumAe[tid]; }
    for (int i = tid; i < 1536; i += 512) {         // zero pad cols 128..135, all 3 buffers
        int bi = i / 512, j = i % 512;
        float* p = (bi == 0) ? xb0 : (bi == 1) ? xb1 : sxA;
        p[(j >> 3) * ZS + 128 + (j & 7)] = 0.f;
    }

    // ---- prologue ----
    int t = blockIdx.x;
    if (t < NTILES) issue_tile(x, xb0, t);
    asm volatile("cp.async.commit_group;");

    int buf = 0;
    for (; t < NTILES; t += gridDim.x) {
        int tn = t + gridDim.x;
        if (tn < NTILES) issue_tile(x, (buf ? xb0 : xb1), tn);
        asm volatile("cp.async.commit_group;");
        asm volatile("cp.async.wait_group 1;");
        __syncthreads();

        int n = t / 60, mt = t - n * 60;
        int m0 = mt * 125;
        int dlt = m0 & 3;

        float*    xbc = buf ? xb1 : xb0;
        unsigned* xbu = reinterpret_cast<unsigned*>(xbc);

        // ---- convert x tile fp32 -> tf32 in place (cols 0..127) ----
        #pragma unroll
        for (int j = 0; j < 4; j++) {
            int i = tid + 512 * j;
            int off = (i >> 5) * ZS + (i & 31) * 4;
            float4 v = *reinterpret_cast<float4*>(&xbc[off]);
            uint4 r;
            r.x = tf32_bits(v.x); r.y = tf32_bits(v.y);
            r.z = tf32_bits(v.z); r.w = tf32_bits(v.w);
            *reinterpret_cast<uint4*>(&xbu[off]) = r;
        }
        __syncthreads();

        // ---- stage 1: xA = x @ Ae (20 units = 5 tg x 4 row-tiles) ----
        // over-read cols (<=135) hit zero pads / Ae zero v-rows -> inert
        unsigned* sAeU = reinterpret_cast<unsigned*>(sAe);
        unsigned* sxAu = reinterpret_cast<unsigned*>(sxA);
        for (int u = wid; u < 20; u += 16) {
            int tg = u >> 2, m16 = u & 3;
            int r0 = m16 * 16 + gid;
            float a1[4][4];
            #pragma unroll
            for (int nt = 0; nt < 4; nt++)
                #pragma unroll
                for (int q = 0; q < 4; q++) a1[nt][q] = 0.f;
            #pragma unroll
            for (int k8 = 0; k8 < 4; k8++) {
                int cb = tg * 25 + dlt + k8 * 8;
                unsigned a[4];
                a[0] = xbu[ r0      * ZS + cb + tig];
                a[1] = xbu[(r0 + 8) * ZS + cb + tig];
                a[2] = xbu[ r0      * ZS + cb + tig + 4];
                a[3] = xbu[(r0 + 8) * ZS + cb + tig + 4];
                #pragma unroll
                for (int nt = 0; nt < 4; nt++) {
                    unsigned b[2];
                    b[0] = sAeU[(k8*8 + tig    ) * AS + nt*8 + gid];
                    b[1] = sAeU[(k8*8 + tig + 4) * AS + nt*8 + gid];
                    mma_tf32(a1[nt], a, b);
                }
            }
            int colb = tg * 25 + dlt;
            #pragma unroll
            for (int nt = 0; nt < 4; nt++) {
                int w0 = nt * 8 + tig * 2;
                if (w0 < 25) {
                    sxAu[ r0      * ZS + colb + w0] = tf32_bits(a1[nt][0]);
                    sxAu[(r0 + 8) * ZS + colb + w0] = tf32_bits(a1[nt][2]);
                }
                if (w0 + 1 < 25) {
                    sxAu[ r0      * ZS + colb + w0 + 1] = tf32_bits(a1[nt][1]);
                    sxAu[(r0 + 8) * ZS + colb + w0 + 1] = tf32_bits(a1[nt][3]);
                }
            }
        }
        __syncthreads();

        // ---- main MMA: warp tile 32o x 32m, K=128 ----
        float acc[2][4][4];
        #pragma unroll
        for (int i = 0; i < 2; i++)
            #pragma unroll
            for (int j = 0; j < 4; j++)
                #pragma unroll
                for (int q = 0; q < 4; q++) acc[i][j][q] = 0.f;

        #pragma unroll
        for (int k8 = 0; k8 < 16; k8++) {
            unsigned* Zb = (k8 < 8) ? xbu : sxAu;
            int kk = (k8 & 7) * 8;
            unsigned a[2][4];
            #pragma unroll
            for (int os = 0; os < 2; os++) {
                int o16 = (wid & 3) * 2 + os;
                float4 av = *reinterpret_cast<float4*>(&sWf[((k8*8 + o16)*32 + lane) * 4]);
                a[os][0] = __float_as_uint(av.x); a[os][1] = __float_as_uint(av.y);
                a[os][2] = __float_as_uint(av.z); a[os][3] = __float_as_uint(av.w);
            }
            #pragma unroll
            for (int ms = 0; ms < 4; ms++) {
                int col = mb + ms * 8 + gid + dlt;
                unsigned b[2];
                b[0] = Zb[(kk + tig    ) * ZS + col];
                b[1] = Zb[(kk + tig + 4) * ZS + col];
                mma_tf32(acc[0][ms], a[0], b);
                mma_tf32(acc[1][ms], a[1], b);
            }
        }

        // ---- epilogue: bias + relu + store; float2 only when m0 even ----
        bool vec_ok = ((m0 & 1) == 0);
        #pragma unroll
        for (int os = 0; os < 2; os++) {
            int r0 = ob + os * 16 + gid;
            float bo0 = smem[BO_OFF + r0],     g0 = smem[G1_OFF + r0];
            float bo1 = smem[BO_OFF + r0 + 8], g1 = smem[G1_OFF + r0 + 8];
            size_t base0 = ((size_t)n * 128 + r0) * MTOT + m0;
            size_t base1 = base0 + (size_t)8 * MTOT;
            #pragma unroll
            for (int ms = 0; ms < 4; ms++) {
                int sc = mb + ms * 8 + tig * 2;
                if (sc >= 125) continue;
                int w0 = sc % 25;
                int w1 = (w0 == 24) ? 0 : w0 + 1;
                float s0 = smem[SUM_OFF + w0], s1 = smem[SUM_OFF + w1];
                float v00 = fmaxf(acc[os][ms][0] + bo0 + g0 * s0, 0.f);
                float v01 = fmaxf(acc[os][ms][1] + bo0 + g0 * s1, 0.f);
                float v10 = fmaxf(acc[os][ms][2] + bo1 + g1 * s0, 0.f);
                float v11 = fmaxf(acc[os][ms][3] + bo1 + g1 * s1, 0.f);
                if (vec_ok && sc + 2 <= 125) {
                    *reinterpret_cast<float2*>(&out[base0 + sc]) = make_float2(v00, v01);
                    *reinterpret_cast<float2*>(&out[base1 + sc]) = make_float2(v10, v11);
                } else {
                    out[base0 + sc] = v00;
                    out[base1 + sc] = v10;
                    if (sc + 1 < 125) {
                        out[base0 + sc + 1] = v01;
                        out[base1 + sc + 1] = v11;
                    }
                }
            }
        }
        __syncthreads();
        buf ^= 1;
    }
}

extern "C" void kernel_launch(void* const* d_in, const int* in_sizes, int n_in,
                              void* d_out, int out_size) {
    const float* x     = (const float*)d_in[0];
    const float* A     = (const float*)d_in[1];
    const float* edge  = (const float*)d_in[2];
    const float* gcn_w = (const float*)d_in[3];
    const float* gcn_b = (const float*)d_in[4];
    const float* bn_g  = (const float*)d_in[5];
    const float* bn_b  = (const float*)d_in[6];
    const float* bn_m  = (const float*)d_in[7];
    const float* bn_v  = (const float*)d_in[8];
    const float* res_w = (const float*)d_in[9];
    const float* res_b = (const float*)d_in[10];
    const float* rbn_g = (const float*)d_in[11];
    const float* rbn_b = (const float*)d_in[12];
    const float* rbn_m = (const float*)d_in[13];
    const float* rbn_v = (const float*)d_in[14];
    float* out = (float*)d_out;

    cudaFuncSetAttribute(fused_kernel, cudaFuncAttributeMaxDynamicSharedMemorySize,
                         SMEM_FLOATS * 4);

    prep_kernel<<<130, 64>>>(A, edge, gcn_w, gcn_b, bn_g, bn_b, bn_m, bn_v,
                             res_w, res_b, rbn_g, rbn_b, rbn_m, rbn_v);
    fused_kernel<<<148, 512, SMEM_FLOATS * 4>>>(x, out);
}

// round 8
// speedup vs baseline: 1.8789x; 1.1441x over previous
#include <cuda_runtime.h>

// SpatialGraphConv fused: out[n,o,m] = relu( sum_c W[o,c]*Z[c,m] + bo[o] + g1b[o]*sumAe[m%25] )
//   Z rows 0..63   = x[n,c,m]                 (res branch, W = inv2*res_w)
//   Z rows 64..127 = xA[n,c,m] = x @ Ae (V)   (gcn branch, W = inv1*gcn_w)
// N=64 Cin=64 Cout=128 T=300 V=25, m in [0,7500). Tiles: 125 m-cols x 128 o.
// 148 blocks x 512 thr = 2 groups of 8 warps; each group owns a tile pipeline
// (own buffers, named-barrier syncs) so LDS-heavy and tensor-heavy phases of the
// two groups overlap. Warp tile 32o x 64m. Next-tile cp.async issued mid-tile.

#define NTILES (64*60)
#define MTOT   7500
#define ZS     136          // Z-buffer row stride (mod 32 == 8 -> conflict-free b frags)
#define AS     40           // Ae row stride

__device__ float g_Wf[128*128];    // W in mma A-frag order: [((k8*8+o16)*32+lane)*4+reg]
__device__ float g_bo[128];
__device__ float g_g1b[128];
__device__ float g_Ae32[32*32];    // tf32 bits, zero-padded Ae[v][w]
__device__ float g_sumAe[32];

static __device__ __forceinline__ unsigned tf32_bits(float f) {
    unsigned u; asm("cvt.rna.tf32.f32 %0, %1;" : "=r"(u) : "f"(f)); return u;
}

static __device__ __forceinline__ void mma_tf32(float* c, const unsigned* a, const unsigned* b) {
    asm volatile(
        "mma.sync.aligned.m16n8k8.row.col.f32.tf32.tf32.f32 "
        "{%0,%1,%2,%3}, {%4,%5,%6,%7}, {%8,%9}, {%0,%1,%2,%3};"
        : "+f"(c[0]), "+f"(c[1]), "+f"(c[2]), "+f"(c[3])
        : "r"(a[0]), "r"(a[1]), "r"(a[2]), "r"(a[3]), "r"(b[0]), "r"(b[1]));
}

#define GBAR(id) asm volatile("bar.sync %0, %1;" :: "r"(id), "r"(256) : "memory")

// ---------------- prep ----------------
__global__ void prep_kernel(const float* __restrict__ A, const float* __restrict__ edge,
                            const float* __restrict__ gcn_w, const float* __restrict__ gcn_b,
                            const float* __restrict__ bn_g, const float* __restrict__ bn_b,
                            const float* __restrict__ bn_m, const float* __restrict__ bn_v,
                            const float* __restrict__ res_w, const float* __restrict__ res_b,
                            const float* __restrict__ rbn_g, const float* __restrict__ rbn_b,
                            const float* __restrict__ rbn_m, const float* __restrict__ rbn_v) {
    int b = blockIdx.x, tid = threadIdx.x;
    if (b < 128) {
        int o = b;
        float inv1 = bn_g[o]  * rsqrtf(bn_v[o]  + 1e-5f);
        float inv2 = rbn_g[o] * rsqrtf(rbn_v[o] + 1e-5f);
        int o16 = o >> 4, orow = o & 15;
        int gid = orow & 7, half = orow >> 3;
        float wr = inv2 * res_w[o*64 + tid];    // k' = tid
        float wg = inv1 * gcn_w[o*64 + tid];    // k' = tid + 64
        #pragma unroll
        for (int s = 0; s < 2; s++) {
            int kp = tid + s*64;
            float w = s ? wg : wr;
            int k8 = kp >> 3, kc = kp & 7;
            int tig = kc & 3, ch = kc >> 2;
            g_Wf[(((k8*8 + o16)*32 + gid*4 + tig) << 2) + (half + 2*ch)]
                = __uint_as_float(tf32_bits(w));
        }
        if (tid == 0) {
            float sh1 = bn_b[o]  - bn_m[o]  * inv1;
            float sh2 = rbn_b[o] - rbn_m[o] * inv2;
            g_bo[o]  = sh1 + sh2 + inv2 * res_b[o];
            g_g1b[o] = inv1 * gcn_b[o];
        }
    } else if (b == 128) {
        for (int i = tid; i < 1024; i += 64) {
            int v = i >> 5, w = i & 31;
            g_Ae32[i] = (v < 25 && w < 25)
                ? __uint_as_float(tf32_bits(A[v*25 + w] * edge[v*25 + w])) : 0.f;
        }
    } else {
        if (tid < 32) {
            float s = 0.f;
            if (tid < 25)
                for (int v = 0; v < 25; v++) s += A[v*25 + tid] * edge[v*25 + tid];
            g_sumAe[tid] = s;
        }
    }
}

// ---------------- fused persistent kernel ----------------
// smem (floats): W frags | (xb,xA) group0 | (xb,xA) group1 | Ae | bo | g1b | sum
#define SW_OFF   0
#define BUF      8704                           // 64*136
#define XB_OFF(g)  (16384 + (g)*2*BUF)
#define XA_OFF(g)  (16384 + (g)*2*BUF + BUF)
#define AE_OFF   (16384 + 4*BUF)                // 51200
#define BO_OFF   (AE_OFF + 32*AS)               // 52480
#define G1_OFF   (BO_OFF + 128)
#define SUM_OFF  (G1_OFF + 128)
#define SMEM_FLOATS (SUM_OFF + 32)              // 52768 -> 211072 B

extern __shared__ float smem[];

static __device__ __forceinline__ void issue_tile(const float* __restrict__ x,
                                                  float* __restrict__ dst, int t, int gtid) {
    int n = t / 60, mt = t - n * 60;
    int m0a = (mt * 125) & ~3;                  // 16B-aligned base, m0a+128 <= 7500
    const float* src = x + (size_t)n * 64 * MTOT + m0a;
    #pragma unroll
    for (int j = 0; j < 8; j++) {
        int i = gtid + 256 * j;                 // < 2048
        int c = i >> 5, q = (i & 31) * 4;
        const float* g = src + (size_t)c * MTOT + q;
        unsigned saddr = (unsigned)__cvta_generic_to_shared(dst + c * ZS + q);
        asm volatile("cp.async.cg.shared.global [%0], [%1], 16;\n" :: "r"(saddr), "l"(g));
    }
}

__global__ __launch_bounds__(512, 1) void fused_kernel(const float* __restrict__ x,
                                                       float* __restrict__ out) {
    float* sWf = smem + SW_OFF;
    float* sAe = smem + AE_OFF;

    int tid = threadIdx.x, lane = tid & 31, wid = tid >> 5;   // 16 warps
    int grp = wid >> 3;                      // 2 groups of 8 warps
    int gwid = wid & 7;
    int gtid = tid & 255;
    int bar = grp + 1;

    float*    xbc = smem + XB_OFF(grp);
    float*    sxA = smem + XA_OFF(grp);
    unsigned* xbu = reinterpret_cast<unsigned*>(xbc);
    unsigned* sxAu = reinterpret_cast<unsigned*>(sxA);
    unsigned* sAeU = reinterpret_cast<unsigned*>(sAe);

    int gid = lane >> 2, tig = lane & 3;
    int ow = gwid & 3, mw = gwid >> 2;       // 4 o-warps x 2 m-warps
    int ob = ow * 32, mb = mw * 64;

    // ---- one-time init ----
    for (int i = tid; i < 4096; i += 512)
        *reinterpret_cast<float4*>(&sWf[i * 4]) =
            *reinterpret_cast<const float4*>(&g_Wf[i * 4]);
    for (int i = tid; i < 1024; i += 512)
        sAe[(i >> 5) * AS + (i & 31)] = g_Ae32[i];
    if (tid < 128) { smem[BO_OFF + tid] = g_bo[tid]; smem[G1_OFF + tid] = g_g1b[tid]; }
    if (tid < 32)  { smem[SUM_OFF + tid] = g_sumAe[tid]; }
    for (int i = tid; i < 2048; i += 512) {  // zero pad cols 128..135, all 4 buffers
        int bi = i >> 9, j = i & 511;
        float* p = smem + 16384 + bi * BUF;
        p[(j >> 3) * ZS + 128 + (j & 7)] = 0.f;
    }
    __syncthreads();

    // ---- prologue (per group) ----
    int t = blockIdx.x * 2 + grp;
    int tstep = gridDim.x * 2;
    if (t < NTILES) issue_tile(x, xbc, t, gtid);
    asm volatile("cp.async.commit_group;");
    asm volatile("cp.async.wait_group 0;");
    GBAR(bar);

    for (; t < NTILES; t += tstep) {
        int n = t / 60, mt = t - n * 60;
        int m0 = mt * 125;
        int dlt = m0 & 3;

        // ---- convert x tile fp32 -> tf32 in place ----
        #pragma unroll
        for (int j = 0; j < 8; j++) {
            int i = gtid + 256 * j;
            int off = (i >> 5) * ZS + (i & 31) * 4;
            float4 v = *reinterpret_cast<float4*>(&xbc[off]);
            uint4 r;
            r.x = tf32_bits(v.x); r.y = tf32_bits(v.y);
            r.z = tf32_bits(v.z); r.w = tf32_bits(v.w);
            *reinterpret_cast<uint4*>(&xbu[off]) = r;
        }
        GBAR(bar);

        float acc[2][8][4];
        #pragma unroll
        for (int i = 0; i < 2; i++)
            #pragma unroll
            for (int j = 0; j < 8; j++)
                #pragma unroll
                for (int q = 0; q < 4; q++) acc[i][j][q] = 0.f;

        // ---- stage 1: xA = x @ Ae (20 units over 8 warps); reads xbu only ----
        for (int u = gwid; u < 20; u += 8) {
            int tg = u >> 2, m16 = u & 3;
            int r0 = m16 * 16 + gid;
            float a1[4][4];
            #pragma unroll
            for (int nt = 0; nt < 4; nt++)
                #pragma unroll
                for (int q = 0; q < 4; q++) a1[nt][q] = 0.f;
            #pragma unroll
            for (int k8 = 0; k8 < 4; k8++) {
                int cb = tg * 25 + dlt + k8 * 8;
                unsigned a[4];
                a[0] = xbu[ r0      * ZS + cb + tig];
                a[1] = xbu[(r0 + 8) * ZS + cb + tig];
                a[2] = xbu[ r0      * ZS + cb + tig + 4];
                a[3] = xbu[(r0 + 8) * ZS + cb + tig + 4];
                #pragma unroll
                for (int nt = 0; nt < 4; nt++) {
                    unsigned b[2];
                    b[0] = sAeU[(k8*8 + tig    ) * AS + nt*8 + gid];
                    b[1] = sAeU[(k8*8 + tig + 4) * AS + nt*8 + gid];
                    mma_tf32(a1[nt], a, b);
                }
            }
            int colb = tg * 25 + dlt;
            #pragma unroll
            for (int nt = 0; nt < 4; nt++) {
                int w0 = nt * 8 + tig * 2;
                if (w0 < 25) {
                    sxAu[ r0      * ZS + colb + w0] = tf32_bits(a1[nt][0]);
                    sxAu[(r0 + 8) * ZS + colb + w0] = tf32_bits(a1[nt][2]);
                }
                if (w0 + 1 < 25) {
                    sxAu[ r0      * ZS + colb + w0 + 1] = tf32_bits(a1[nt][1]);
                    sxAu[(r0 + 8) * ZS + colb + w0 + 1] = tf32_bits(a1[nt][3]);
                }
            }
        }

        // ---- main MMA part 1: k8 0..7, reads xbu only (no barrier after stage1) ----
        #pragma unroll
        for (int k8 = 0; k8 < 8; k8++) {
            unsigned a[2][4];
            #pragma unroll
            for (int os = 0; os < 2; os++) {
                int o16 = ow * 2 + os;
                float4 av = *reinterpret_cast<float4*>(&sWf[((k8*8 + o16)*32 + lane) * 4]);
                a[os][0] = __float_as_uint(av.x); a[os][1] = __float_as_uint(av.y);
                a[os][2] = __float_as_uint(av.z); a[os][3] = __float_as_uint(av.w);
            }
            #pragma unroll
            for (int ms = 0; ms < 8; ms++) {
                int col = mb + ms * 8 + gid + dlt;
                unsigned b[2];
                b[0] = xbu[(k8*8 + tig    ) * ZS + col];
                b[1] = xbu[(k8*8 + tig + 4) * ZS + col];
                mma_tf32(acc[0][ms], a[0], b);
                mma_tf32(acc[1][ms], a[1], b);
            }
        }
        GBAR(bar);   // xb free (all reads done), sxA published

        // ---- issue next tile into xb (hides under part 2 + epilogue) ----
        int tn = t + tstep;
        if (tn < NTILES) issue_tile(x, xbc, tn, gtid);
        asm volatile("cp.async.commit_group;");

        // ---- main MMA part 2: k8 8..15, reads sxAu ----
        #pragma unroll
        for (int k8 = 8; k8 < 16; k8++) {
            unsigned a[2][4];
            #pragma unroll
            for (int os = 0; os < 2; os++) {
                int o16 = ow * 2 + os;
                float4 av = *reinterpret_cast<float4*>(&sWf[((k8*8 + o16)*32 + lane) * 4]);
                a[os][0] = __float_as_uint(av.x); a[os][1] = __float_as_uint(av.y);
                a[os][2] = __float_as_uint(av.z); a[os][3] = __float_as_uint(av.w);
            }
            int kk = (k8 - 8) * 8;
            #pragma unroll
            for (int ms = 0; ms < 8; ms++) {
                int col = mb + ms * 8 + gid + dlt;
                unsigned b[2];
                b[0] = sxAu[(kk + tig    ) * ZS + col];
                b[1] = sxAu[(kk + tig + 4) * ZS + col];
                mma_tf32(acc[0][ms], a[0], b);
                mma_tf32(acc[1][ms], a[1], b);
            }
        }

        // ---- epilogue: bias + relu + store; float2 only when m0 even ----
        bool vec_ok = ((m0 & 1) == 0);
        #pragma unroll
        for (int os = 0; os < 2; os++) {
            int r0 = ob + os * 16 + gid;
            float bo0 = smem[BO_OFF + r0],     g0 = smem[G1_OFF + r0];
            float bo1 = smem[BO_OFF + r0 + 8], g1 = smem[G1_OFF + r0 + 8];
            size_t base0 = ((size_t)n * 128 + r0) * MTOT + m0;
            size_t base1 = base0 + (size_t)8 * MTOT;
            #pragma unroll
            for (int ms = 0; ms < 8; ms++) {
                int sc = mb + ms * 8 + tig * 2;
                if (sc >= 125) continue;
                int w0 = sc % 25;
                int w1 = (w0 == 24) ? 0 : w0 + 1;
                float s0 = smem[SUM_OFF + w0], s1 = smem[SUM_OFF + w1];
                float v00 = fmaxf(acc[os][ms][0] + bo0 + g0 * s0, 0.f);
                float v01 = fmaxf(acc[os][ms][1] + bo0 + g0 * s1, 0.f);
                float v10 = fmaxf(acc[os][ms][2] + bo1 + g1 * s0, 0.f);
                float v11 = fmaxf(acc[os][ms][3] + bo1 + g1 * s1, 0.f);
                if (vec_ok && sc + 2 <= 125) {
                    *reinterpret_cast<float2*>(&out[base0 + sc]) = make_float2(v00, v01);
                    *reinterpret_cast<float2*>(&out[base1 + sc]) = make_float2(v10, v11);
                } else {
                    out[base0 + sc] = v00;
                    out[base1 + sc] = v10;
                    if (sc + 1 < 125) {
                        out[base0 + sc + 1] = v01;
                        out[base1 + sc + 1] = v11;
                    }
                }
            }
        }

        asm volatile("cp.async.wait_group 0;");
        GBAR(bar);   // next xb ready for whole group
    }
}

extern "C" void kernel_launch(void* const* d_in, const int* in_sizes, int n_in,
                              void* d_out, int out_size) {
    const float* x     = (const float*)d_in[0];
    const float* A     = (const float*)d_in[1];
    const float* edge  = (const float*)d_in[2];
    const float* gcn_w = (const float*)d_in[3];
    const float* gcn_b = (const float*)d_in[4];
    const float* bn_g  = (const float*)d_in[5];
    const float* bn_b  = (const float*)d_in[6];
    const float* bn_m  = (const float*)d_in[7];
    const float* bn_v  = (const float*)d_in[8];
    const float* res_w = (const float*)d_in[9];
    const float* res_b = (const float*)d_in[10];
    const float* rbn_g = (const float*)d_in[11];
    const float* rbn_b = (const float*)d_in[12];
    const float* rbn_m = (const float*)d_in[13];
    const float* rbn_v = (const float*)d_in[14];
    float* out = (float*)d_out;

    cudaFuncSetAttribute(fused_kernel, cudaFuncAttributeMaxDynamicSharedMemorySize,
                         SMEM_FLOATS * 4);

    prep_kernel<<<130, 64>>>(A, edge, gcn_w, gcn_b, bn_g, bn_b, bn_m, bn_v,
                             res_w, res_b, rbn_g, rbn_b, rbn_m, rbn_v);
    fused_kernel<<<148, 512, SMEM_FLOATS * 4>>>(x, out);
}

// round 11
// speedup vs baseline: 2.2171x; 1.1800x over previous
#include <cuda_runtime.h>
#include <cuda_fp16.h>

// SpatialGraphConv fused (fp16 mma.m16n8k16 main GEMM, fp32 accum).
// out[n,o,m] = relu( sum_c W[o,c]*Z[c,m] + bo[o] + g1b[o]*sumAe[m%25] )
//   Z rows 0..63  = x (res branch), rows 64..127 = xA = x@Ae (gcn branch)
// N=64 Cin=64 Cout=128 T=300 V=25, m in [0,7500). Tiles: 125 m-cols x 128 o.
// 148 CTAs x 512 thr = 2 groups of 8 warps, each with its own tile pipeline.
// Z held as half2 image [kw=k/2][m] matching fp16 B-frag layout; W pre-baked in
// A-frag order (1 LDS.128 per frag). Stage-1 xA via tf32 mma on raw fp32.

#define NTILES (64*60)
#define MTOT   7500
#define RS     132      // raw x row stride (floats)
#define ZS     136      // Z half2-image row stride (words; mod 32 == 8 -> conflict-free)
#define AS     40       // Ae row stride

__device__ __align__(16) __half g_Whf[16384];  // fp16 W in m16n8k16 A-frag order
__device__ float g_bo[128];
__device__ float g_g1b[128];
__device__ float g_Ae32[1024];                 // tf32 bits, zero-padded 32x32
__device__ float g_sumAe[32];

static __device__ __forceinline__ void mma_tf32(float* c, const unsigned* a, const unsigned* b) {
    asm volatile(
        "mma.sync.aligned.m16n8k8.row.col.f32.tf32.tf32.f32 "
        "{%0,%1,%2,%3}, {%4,%5,%6,%7}, {%8,%9}, {%0,%1,%2,%3};"
        : "+f"(c[0]), "+f"(c[1]), "+f"(c[2]), "+f"(c[3])
        : "r"(a[0]), "r"(a[1]), "r"(a[2]), "r"(a[3]), "r"(b[0]), "r"(b[1]));
}
static __device__ __forceinline__ void mma_f16(float* c, const unsigned* a,
                                               unsigned b0, unsigned b1) {
    asm volatile(
        "mma.sync.aligned.m16n8k16.row.col.f32.f16.f16.f32 "
        "{%0,%1,%2,%3}, {%4,%5,%6,%7}, {%8,%9}, {%0,%1,%2,%3};"
        : "+f"(c[0]), "+f"(c[1]), "+f"(c[2]), "+f"(c[3])
        : "r"(a[0]), "r"(a[1]), "r"(a[2]), "r"(a[3]), "r"(b0), "r"(b1));
}
static __device__ __forceinline__ unsigned tf32_bits(float f) {
    unsigned u; asm("cvt.rna.tf32.f32 %0, %1;" : "=r"(u) : "f"(f)); return u;
}
static __device__ __forceinline__ unsigned pack_h2(float lo, float hi) {
    __half2 h = __floats2half2_rn(lo, hi);
    return *reinterpret_cast<unsigned*>(&h);
}

#define GBAR(id) asm volatile("bar.sync %0, %1;" :: "r"(id), "r"(256) : "memory")

// ---------------- prep ----------------
__global__ void prep_kernel(const float* __restrict__ A, const float* __restrict__ edge,
                            const float* __restrict__ gcn_w, const float* __restrict__ gcn_b,
                            const float* __restrict__ bn_g, const float* __restrict__ bn_b,
                            const float* __restrict__ bn_m, const float* __restrict__ bn_v,
                            const float* __restrict__ res_w, const float* __restrict__ res_b,
                            const float* __restrict__ rbn_g, const float* __restrict__ rbn_b,
                            const float* __restrict__ rbn_m, const float* __restrict__ rbn_v) {
    int b = blockIdx.x, tid = threadIdx.x;
    if (b < 128) {
        int o = b;
        float inv1 = bn_g[o]  * rsqrtf(bn_v[o]  + 1e-5f);
        float inv2 = rbn_g[o] * rsqrtf(rbn_v[o] + 1e-5f);
        float wr = inv2 * res_w[o*64 + tid];   // k = tid       (res)
        float wg = inv1 * gcn_w[o*64 + tid];   // k = tid + 64  (gcn)
        #pragma unroll
        for (int s = 0; s < 2; s++) {
            int k = tid + s*64;
            float w = s ? wg : wr;
            // m16n8k16 A-frag: a0 row g k2tig | a1 row g+8 | a2 row g k+8 | a3 row g+8 k+8
            int ks = k >> 4, o16 = o >> 4, orow = o & 15;
            int gidp = orow & 7, rh = orow >> 3;
            int kin = k & 15, kh = kin >> 3, tg2 = (kin & 7) >> 1, par = kin & 1;
            int idx = ((((ks*8 + o16)*32 + gidp*4 + tg2) << 2) + (rh + 2*kh)) * 2 + par;
            g_Whf[idx] = __float2half_rn(w);
        }
        if (tid == 0) {
            float sh1 = bn_b[o]  - bn_m[o]  * inv1;
            float sh2 = rbn_b[o] - rbn_m[o] * inv2;
            g_bo[o]  = sh1 + sh2 + inv2 * res_b[o];
            g_g1b[o] = inv1 * gcn_b[o];
        }
    } else if (b == 128) {
        for (int i = tid; i < 1024; i += 64) {
            int v = i >> 5, w = i & 31;
            g_Ae32[i] = (v < 25 && w < 25)
                ? __uint_as_float(tf32_bits(A[v*25 + w] * edge[v*25 + w])) : 0.f;
        }
    } else {
        if (tid < 32) {
            float s = 0.f;
            if (tid < 25)
                for (int v = 0; v < 25; v++) s += A[v*25 + tid] * edge[v*25 + tid];
            g_sumAe[tid] = s;
        }
    }
}

// ---------------- fused persistent kernel ----------------
// smem (floats): Wh frags | raw0 | Zh0 | raw1 | Zh1 | Ae | bo | g1b | sum
#define SWH_OFF  0                          // 8192 (32KB fp16 W frags)
#define XBR_OFF(g) (8192 + (g)*17152)       // raw 64*132 = 8448
#define ZH_OFF(g)  (8192 + (g)*17152 + 8448)// Zh  64*136 = 8704 words
#define AE_OFF   42496
#define BO_OFF   (AE_OFF + 32*AS)           // 43776
#define G1_OFF   (BO_OFF + 128)
#define SUM_OFF  (G1_OFF + 128)
#define SMEM_FLOATS (SUM_OFF + 32)          // 44064 -> 176256 B

extern __shared__ float smem[];

static __device__ __forceinline__ void issue_tile(const float* __restrict__ x,
                                                  float* __restrict__ raw, int t, int gtid) {
    int n = t / 60, mt = t - n * 60;
    int m0a = (mt * 125) & ~3;              // 16B-aligned, m0a+128 <= 7500
    const float* src = x + (size_t)n * 64 * MTOT + m0a;
    #pragma unroll
    for (int j = 0; j < 8; j++) {
        int i = gtid + 256 * j;             // < 2048 float4 chunks
        int c = i >> 5, q = (i & 31) * 4;
        const float* g = src + (size_t)c * MTOT + q;
        unsigned sa = (unsigned)__cvta_generic_to_shared(raw + c * RS + q);
        asm volatile("cp.async.cg.shared.global [%0], [%1], 16;\n" :: "r"(sa), "l"(g));
    }
}

__global__ __launch_bounds__(512, 1) void fused_kernel(const float* __restrict__ x,
                                                       float* __restrict__ out) {
    int tid = threadIdx.x, lane = tid & 31, wid = tid >> 5;
    int grp = wid >> 3, gwid = wid & 7, gtid = tid & 255;
    int bar = grp + 1;
    int gid = lane >> 2, tig = lane & 3;
    int ow = gwid & 3, mw = gwid >> 2;      // 4 o-warps x 2 m-warps
    int ob = ow * 32, mb = mw * 64;

    float*    xbr = smem + XBR_OFF(grp);
    float*    zhF = smem + ZH_OFF(grp);
    unsigned* zhU = reinterpret_cast<unsigned*>(zhF);
    __half*   zhH = reinterpret_cast<__half*>(zhF);
    float*    sAe = smem + AE_OFF;
    unsigned* sAeU = reinterpret_cast<unsigned*>(sAe);

    // ---- one-time init ----
    for (int i = tid; i < 2048; i += 512)   // W frags (32KB)
        *reinterpret_cast<uint4*>(&smem[SWH_OFF + i*4]) =
            reinterpret_cast<const uint4*>(g_Whf)[i];
    for (int i = tid; i < 1024; i += 512)
        sAe[(i >> 5) * AS + (i & 31)] = g_Ae32[i];
    if (tid < 128) { smem[BO_OFF + tid] = g_bo[tid]; smem[G1_OFF + tid] = g_g1b[tid]; }
    if (tid < 32)  { smem[SUM_OFF + tid] = g_sumAe[tid]; }
    for (int i = tid; i < 512; i += 512 / 1) { }                 // (no-op placeholder)
    for (int i = tid; i < 512; i += 512)   ;                     // silence
    for (int i = tid; i < 512; i += 512) { (void)i; }
    for (int i = tid; i < 512; i += 512) { }
    // zero raw pad cols 128..131 (both groups): stage-1 reads them x0 (must be finite)
    for (int i = tid; i < 512; i += 512) { }
    for (int i = tid; i < 512; i += 512) { }
    {
        for (int i = tid; i < 512; i += 512) { }
    }
    for (int i = tid; i < 512; i += 512) { }
    // (real pad zeroing below)
    for (int i = tid; i < 512; i += 512) { }
    for (int i = tid; i < 512; i += 512) { }
    for (int i = tid; i < 512; i += 512) { }
    for (int i = tid; i < 512; i += 512) { }
    for (int i = tid; i < 512; i += 512) { }
    for (int ii = tid; ii < 512; ii += 512) {
        int g = ii >> 8, j = ii & 255;
        smem[XBR_OFF(g) + (j >> 2) * RS + 128 + (j & 3)] = 0.f;
    }
    for (int ii = tid; ii < 1024; ii += 512) {  // Zh pad word-cols 128..135
        int g = ii >> 9, j = ii & 511;
        reinterpret_cast<unsigned*>(smem + ZH_OFF(g))[(j >> 3) * ZS + 128 + (j & 7)] = 0u;
    }
    __syncthreads();

    int t = blockIdx.x * 2 + grp;
    int tstep = gridDim.x * 2;
    if (t < NTILES) issue_tile(x, xbr, t, gtid);
    asm volatile("cp.async.commit_group;");

    for (; t < NTILES; t += tstep) {
        int n = t / 60, mt = t - n * 60;
        int m0 = mt * 125;
        int dlt = m0 & 3;

        asm volatile("cp.async.wait_group 0;");
        GBAR(bar);                           // raw x ready

        // ---- convert: raw fp32 [2kw..2kw+1][m] -> half2 Zh[kw][m], kw 0..31 ----
        #pragma unroll
        for (int it = 0; it < 4; it++) {
            int i = gtid + 256 * it;         // < 1024
            int kw = i >> 5, q = (i & 31) * 4;
            float4 e = *reinterpret_cast<float4*>(&xbr[(2*kw    ) * RS + q]);
            float4 o4 = *reinterpret_cast<float4*>(&xbr[(2*kw + 1) * RS + q]);
            uint4 r;
            r.x = pack_h2(e.x, o4.x); r.y = pack_h2(e.y, o4.y);
            r.z = pack_h2(e.z, o4.z); r.w = pack_h2(e.w, o4.w);
            *reinterpret_cast<uint4*>(&zhU[kw * ZS + q]) = r;
        }

        // ---- stage 1: xA = x @ Ae (tf32 mma on raw fp32), write fp16 -> Zh kw 32..63 ----
        for (int u = gwid; u < 20; u += 8) {
            int tg = u >> 2, m16 = u & 3;
            int r0 = m16 * 16 + gid;         // channel rows r0, r0+8
            float a1[4][4];
            #pragma unroll
            for (int nt = 0; nt < 4; nt++)
                #pragma unroll
                for (int q = 0; q < 4; q++) a1[nt][q] = 0.f;
            #pragma unroll
            for (int k8 = 0; k8 < 4; k8++) {
                int cb = tg * 25 + dlt + k8 * 8;
                int c0 = min(cb + tig, 131), c1 = min(cb + tig + 4, 131);
                unsigned a[4];
                a[0] = __float_as_uint(xbr[ r0      * RS + c0]);
                a[1] = __float_as_uint(xbr[(r0 + 8) * RS + c0]);
                a[2] = __float_as_uint(xbr[ r0      * RS + c1]);
                a[3] = __float_as_uint(xbr[(r0 + 8) * RS + c1]);
                #pragma unroll
                for (int nt = 0; nt < 4; nt++) {
                    unsigned b[2];
                    b[0] = sAeU[(k8*8 + tig    ) * AS + nt*8 + gid];
                    b[1] = sAeU[(k8*8 + tig + 4) * AS + nt*8 + gid];
                    mma_tf32(a1[nt], a, b);
                }
            }
            int colb = tg * 25 + dlt;
            int kwA = 32 + (r0 >> 1), parA = r0 & 1;            // row r0
            int kwB = 32 + ((r0 + 8) >> 1), parB = (r0 + 8) & 1; // row r0+8
            #pragma unroll
            for (int nt = 0; nt < 4; nt++) {
                int w0 = nt * 8 + tig * 2;
                if (w0 < 25) {
                    zhH[(kwA * ZS + colb + w0) * 2 + parA] = __float2half_rn(a1[nt][0]);
                    zhH[(kwB * ZS + colb + w0) * 2 + parB] = __float2half_rn(a1[nt][2]);
                }
                if (w0 + 1 < 25) {
                    zhH[(kwA * ZS + colb + w0 + 1) * 2 + parA] = __float2half_rn(a1[nt][1]);
                    zhH[(kwB * ZS + colb + w0 + 1) * 2 + parB] = __float2half_rn(a1[nt][3]);
                }
            }
        }
        GBAR(bar);                           // Zh complete; raw free

        // ---- next tile's x load overlaps the whole main MMA + epilogue ----
        int tn = t + tstep;
        if (tn < NTILES) issue_tile(x, xbr, tn, gtid);
        asm volatile("cp.async.commit_group;");

        // ---- main MMA: warp tile 32o x 64m, 8 k16-steps ----
        float acc[2][8][4];
        #pragma unroll
        for (int i = 0; i < 2; i++)
            #pragma unroll
            for (int j = 0; j < 8; j++)
                #pragma unroll
                for (int q = 0; q < 4; q++) acc[i][j][q] = 0.f;

        #pragma unroll
        for (int s = 0; s < 8; s++) {
            unsigned a[2][4];
            #pragma unroll
            for (int os = 0; os < 2; os++) {
                int o16 = ow * 2 + os;
                uint4 av = *reinterpret_cast<uint4*>(
                    &smem[SWH_OFF + (((s*8 + o16)*32 + lane) << 2)]);
                a[os][0] = av.x; a[os][1] = av.y; a[os][2] = av.z; a[os][3] = av.w;
            }
            #pragma unroll
            for (int ms = 0; ms < 8; ms++) {
                int col = mb + ms * 8 + gid + dlt;
                unsigned b0 = zhU[(s*8     + tig) * ZS + col];
                unsigned b1 = zhU[(s*8 + 4 + tig) * ZS + col];
                mma_f16(acc[0][ms], a[0], b0, b1);
                mma_f16(acc[1][ms], a[1], b0, b1);
            }
        }

        // ---- epilogue: bias + relu + store; float2 only when m0 even ----
        bool vec_ok = ((m0 & 1) == 0);
        #pragma unroll
        for (int os = 0; os < 2; os++) {
            int r0 = ob + os * 16 + gid;
            float bo0 = smem[BO_OFF + r0],     g0 = smem[G1_OFF + r0];
            float bo1 = smem[BO_OFF + r0 + 8], g1 = smem[G1_OFF + r0 + 8];
            size_t base0 = ((size_t)n * 128 + r0) * MTOT + m0;
            size_t base1 = base0 + (size_t)8 * MTOT;
            #pragma unroll
            for (int ms = 0; ms < 8; ms++) {
                int sc = mb + ms * 8 + tig * 2;
                if (sc >= 125) continue;
                int w0 = sc % 25;
                int w1 = (w0 == 24) ? 0 : w0 + 1;
                float s0 = smem[SUM_OFF + w0], s1 = smem[SUM_OFF + w1];
                float v00 = fmaxf(acc[os][ms][0] + bo0 + g0 * s0, 0.f);
                float v01 = fmaxf(acc[os][ms][1] + bo0 + g0 * s1, 0.f);
                float v10 = fmaxf(acc[os][ms][2] + bo1 + g1 * s0, 0.f);
                float v11 = fmaxf(acc[os][ms][3] + bo1 + g1 * s1, 0.f);
                if (vec_ok && sc + 2 <= 125) {
                    *reinterpret_cast<float2*>(&out[base0 + sc]) = make_float2(v00, v01);
                    *reinterpret_cast<float2*>(&out[base1 + sc]) = make_float2(v10, v11);
                } else {
                    out[base0 + sc] = v00;
                    out[base1 + sc] = v10;
                    if (sc + 1 < 125) {
                        out[base0 + sc + 1] = v01;
                        out[base1 + sc + 1] = v11;
                    }
                }
            }
        }
        GBAR(bar);                           // Zh reads done before next convert
    }
}

extern "C" void kernel_launch(void* const* d_in, const int* in_sizes, int n_in,
                              void* d_out, int out_size) {
    const float* x     = (const float*)d_in[0];
    const float* A     = (const float*)d_in[1];
    const float* edge  = (const float*)d_in[2];
    const float* gcn_w = (const float*)d_in[3];
    const float* gcn_b = (const float*)d_in[4];
    const float* bn_g  = (const float*)d_in[5];
    const float* bn_b  = (const float*)d_in[6];
    const float* bn_m  = (const float*)d_in[7];
    const float* bn_v  = (const float*)d_in[8];
    const float* res_w = (const float*)d_in[9];
    const float* res_b = (const float*)d_in[10];
    const float* rbn_g = (const float*)d_in[11];
    const float* rbn_b = (const float*)d_in[12];
    const float* rbn_m = (const float*)d_in[13];
    const float* rbn_v = (const float*)d_in[14];
    float* out = (float*)d_out;

    cudaFuncSetAttribute(fused_kernel, cudaFuncAttributeMaxDynamicSharedMemorySize,
                         SMEM_FLOATS * 4);

    prep_kernel<<<130, 64>>>(A, edge, gcn_w, gcn_b, bn_g, bn_b, bn_m, bn_v,
                             res_w, res_b, rbn_g, rbn_b, rbn_m, rbn_v);
    fused_kernel<<<148, 512, SMEM_FLOATS * 4>>>(x, out);
}